// round 1
// baseline (speedup 1.0000x reference)
#include <cuda_runtime.h>
#include <math.h>

#define BB 8
#define LL 1536
#define HH 8
#define EE 64
#define HE 512          // H*E
#define BHE 4096        // B*H*E
#define TOPK 7          // int(log(1536)) = 7

// ---------------- scratch (static __device__, no allocation) ----------------
__device__ float g_qr[(size_t)BHE * LL];   // layernormed q, (b,h,e,l)
__device__ float g_kr[(size_t)BHE * LL];   // layernormed k, (b,h,e,l)
__device__ float g_mean[BB * LL];          // sum over (h,e) of clipped corr
__device__ float g_scal[4];                // [0]=sigmoid(freq), [1..3]=softmax(scale_weights)
__device__ int   g_delays[BB * TOPK];
__device__ float g_nw[BB * TOPK];

__constant__ int c_plan1536[6] = {3,4,4,4,4,2};
__constant__ int c_plan768[5]  = {3,4,4,4,4};
__constant__ int c_plan384[5]  = {3,4,4,4,2};

// ---------------- K0: scalars + zero mean accumulator ----------------
__global__ void k0_init(const float* __restrict__ sw, const float* __restrict__ ff) {
    int idx = blockIdx.x * blockDim.x + threadIdx.x;
    for (int i = idx; i < BB * LL; i += gridDim.x * blockDim.x) g_mean[i] = 0.f;
    if (idx == 0) {
        g_scal[0] = 1.f / (1.f + expf(-ff[0]));
        float a = sw[0], b = sw[1], c = sw[2];
        float mx = fmaxf(a, fmaxf(b, c));
        float ea = expf(a - mx), eb = expf(b - mx), ec = expf(c - mx);
        float s = ea + eb + ec;
        g_scal[1] = ea / s; g_scal[2] = eb / s; g_scal[3] = ec / s;
    }
}

// ---------------- K1: LayerNorm over E + transpose to (b,h,e,l) ----------------
__global__ __launch_bounds__(256) void k1_ln(const float* __restrict__ q,
                                             const float* __restrict__ kk) {
    __shared__ float tile[32][EE + 1];
    __shared__ float mu[32], isd[32];
    int l0 = blockIdx.x * 32;
    int bh = blockIdx.y;                 // b*8 + h
    int b  = bh >> 3, h = bh & 7;
    const float* in = blockIdx.z ? kk : q;
    float* out      = blockIdx.z ? g_kr : g_qr;
    int tid = threadIdx.x;
    int e = tid & 63, r0 = tid >> 6;
    for (int r = r0; r < 32; r += 4)
        tile[r][e] = in[(((size_t)b * LL + l0 + r) * HH + h) * EE + e];
    __syncthreads();
    if (tid < 32) {
        float s = 0.f;
        #pragma unroll 8
        for (int i = 0; i < EE; i++) s += tile[tid][i];
        float m = s * (1.f / EE);
        float v = 0.f;
        #pragma unroll 8
        for (int i = 0; i < EE; i++) { float d = tile[tid][i] - m; v += d * d; }
        v *= (1.f / EE);
        mu[tid] = m; isd[tid] = rsqrtf(v + 1e-5f);
    }
    __syncthreads();
    int li = tid & 31, e0 = tid >> 5;
    for (int ee = e0; ee < EE; ee += 8) {
        float val = (tile[li][ee] - mu[li]) * isd[li];
        out[(((size_t)bh) * EE + ee) * LL + l0 + li] = val;
    }
}

// ---------------- FFT helpers ----------------
__device__ __forceinline__ float2 cmul(float2 a, float2 b) {
    return make_float2(a.x * b.x - a.y * b.y, a.x * b.y + a.y * b.x);
}

// Mixed-radix Stockham DIF forward FFT, 256 threads, ping-pong a<->b.
// After return, `a` points at the result buffer.
__device__ void fft_fwd(float2*& a, float2*& b, int N, const int* plan, int ns, int tid) {
    int l = N, m = 1;
    for (int st = 0; st < ns; st++) {
        int r = plan[st];
        l /= r;
        int nb = l * m;            // N / r butterflies
        int stride = m * l;
        float base = -6.283185307179586f / (float)(r * l);
        for (int t = tid; t < nb; t += 256) {
            int j = t / m;
            int k = t - j * m;
            int rb = k + m * j;
            int wb = k + m * r * j;
            float sw, cw; __sincosf(base * (float)j, &sw, &cw);
            float2 w1 = make_float2(cw, sw);
            if (r == 4) {
                float2 c0 = a[rb], c1 = a[rb + stride], c2 = a[rb + 2 * stride], c3 = a[rb + 3 * stride];
                float2 t0 = {c0.x + c2.x, c0.y + c2.y};
                float2 t1 = {c0.x - c2.x, c0.y - c2.y};
                float2 t2 = {c1.x + c3.x, c1.y + c3.y};
                float2 t3 = {c1.x - c3.x, c1.y - c3.y};
                float2 d0 = {t0.x + t2.x, t0.y + t2.y};
                float2 d2 = {t0.x - t2.x, t0.y - t2.y};
                float2 d1 = {t1.x + t3.y, t1.y - t3.x};   // t1 - i*t3
                float2 d3 = {t1.x - t3.y, t1.y + t3.x};   // t1 + i*t3
                float2 w2 = cmul(w1, w1);
                float2 w3 = cmul(w2, w1);
                b[wb]         = d0;
                b[wb + m]     = cmul(d1, w1);
                b[wb + 2 * m] = cmul(d2, w2);
                b[wb + 3 * m] = cmul(d3, w3);
            } else if (r == 3) {
                float2 c0 = a[rb], c1 = a[rb + stride], c2 = a[rb + 2 * stride];
                float2 t1 = {c1.x + c2.x, c1.y + c2.y};
                float2 u  = {c0.x - 0.5f * t1.x, c0.y - 0.5f * t1.y};
                const float s3 = 0.8660254037844386f;
                float2 v  = {s3 * (c1.x - c2.x), s3 * (c1.y - c2.y)};
                float2 d0 = {c0.x + t1.x, c0.y + t1.y};
                float2 d1 = {u.x + v.y, u.y - v.x};       // u - i*v
                float2 d2 = {u.x - v.y, u.y + v.x};       // u + i*v
                float2 w2 = cmul(w1, w1);
                b[wb]         = d0;
                b[wb + m]     = cmul(d1, w1);
                b[wb + 2 * m] = cmul(d2, w2);
            } else {  // r == 2
                float2 c0 = a[rb], c1 = a[rb + stride];
                b[wb]     = make_float2(c0.x + c1.x, c0.y + c1.y);
                b[wb + m] = cmul(make_float2(c0.x - c1.x, c0.y - c1.y), w1);
            }
        }
        __syncthreads();
        float2* tmp = a; a = b; b = tmp;
        m *= r;
    }
}

// ---------------- K2: per-(b,h,e) 3-scale whitened autocorrelation ----------------
__global__ __launch_bounds__(256) void k2_corr() {
    __shared__ float sq[LL], sk[LL], sacc[LL];
    __shared__ float2 bufA[LL], bufB[LL];
    int tid = threadIdx.x;
    int bhe = blockIdx.x;
    int b = bhe >> 9;   // / (H*E)
    const float* qrow = g_qr + (size_t)bhe * LL;
    const float* krow = g_kr + (size_t)bhe * LL;
    for (int i = tid; i < LL; i += 256) {
        sq[i] = qrow[i]; sk[i] = krow[i]; sacc[i] = 0.f;
    }
    float f = g_scal[0];
    __syncthreads();

    for (int si = 0; si < 3; si++) {
        int s = 1 << si;
        int N = LL >> si;
        // downsample (mean over s consecutive) and pack z = q + i*k
        for (int n = tid; n < N; n += 256) {
            float aq = 0.f, ak = 0.f;
            for (int t = 0; t < s; t++) { aq += sq[n * s + t]; ak += sk[n * s + t]; }
            float inv = 1.f / (float)s;
            bufA[n] = make_float2(aq * inv, ak * inv);
        }
        __syncthreads();

        float2 *a = bufA, *bb = bufB;
        const int* plan = (si == 0) ? c_plan1536 : (si == 1 ? c_plan768 : c_plan384);
        int ns = (si == 0) ? 6 : 5;
        fft_fwd(a, bb, N, plan, ns, tid);   // a = Z

        // Hermitian split + whitened cross-spectrum into bb
        int half = N >> 1;
        for (int w = tid; w <= half; w += 256) {
            float2 Zw = a[w];
            float2 Zm = a[(N - w) % N];
            float Qx = 0.5f * (Zw.x + Zm.x), Qy = 0.5f * (Zw.y - Zm.y);
            float Dx = Zw.x - Zm.x,          Dy = Zw.y + Zm.y;
            float Kx = 0.5f * Dy,            Ky = -0.5f * Dx;
            // res = f^2 * Q * conj(K) / (f*|K| + 1e-8)
            float kmag  = sqrtf(Kx * Kx + Ky * Ky);
            float sc    = f * f / (f * kmag + 1e-8f);
            float Rx = (Qx * Kx + Qy * Ky) * sc;
            float Ry = (Qy * Kx - Qx * Ky) * sc;
            bb[w] = make_float2(Rx, Ry);
            if (w > 0 && w < half) bb[N - w] = make_float2(Rx, -Ry);
        }
        __syncthreads();

        // inverse FFT via forward FFT on Hermitian R: c[x] = A[(N-x)%N].x / N
        float2 *a2 = bb, *b2 = a;
        fft_fwd(a2, b2, N, plan, ns, tid);

        float wgt  = g_scal[1 + si];
        float invN = 1.f / (float)N;
        if (s == 1) {
            for (int l = tid; l < LL; l += 256)
                sacc[l] += wgt * a2[(N - l) % N].x * invN;
        } else {
            float invS = 1.f / (float)s;
            for (int l = tid; l < LL; l += 256) {
                float coords = ((float)l + 0.5f) * invS - 0.5f;
                coords = fminf(fmaxf(coords, 0.f), (float)(N - 1));
                int lo = (int)floorf(coords);
                int hi = min(lo + 1, N - 1);
                float fr  = coords - (float)lo;
                float clo = a2[(N - lo) % N].x;
                float chi = a2[(N - hi) % N].x;
                sacc[l] += wgt * (clo * (1.f - fr) + chi * fr) * invN;
            }
        }
        __syncthreads();
    }

    for (int l = tid; l < LL; l += 256) {
        float v = fminf(fmaxf(sacc[l], -10.f), 10.f);
        atomicAdd(&g_mean[b * LL + l], v);
    }
}

// ---------------- K3: per-batch top-7 + softmax ----------------
__global__ __launch_bounds__(256) void k3_topk() {
    __shared__ float vals[LL];
    __shared__ float rv[256];
    __shared__ int   ri[256];
    __shared__ float wk[TOPK];
    int b = blockIdx.x;
    int tid = threadIdx.x;
    for (int l = tid; l < LL; l += 256) vals[l] = g_mean[b * LL + l] * (1.f / HE);
    __syncthreads();
    for (int it = 0; it < TOPK; it++) {
        float best = -3.0e38f; int bi = 0;
        for (int l = tid; l < LL; l += 256) {
            float v = vals[l];
            if (v > best) { best = v; bi = l; }   // strict > keeps lowest index on ties
        }
        rv[tid] = best; ri[tid] = bi;
        __syncthreads();
        for (int off = 128; off > 0; off >>= 1) {
            if (tid < off) {
                float v2 = rv[tid + off]; int i2 = ri[tid + off];
                if (v2 > rv[tid] || (v2 == rv[tid] && i2 < ri[tid])) { rv[tid] = v2; ri[tid] = i2; }
            }
            __syncthreads();
        }
        if (tid == 0) {
            wk[it] = rv[0];
            g_delays[b * TOPK + it] = ri[0];
            vals[ri[0]] = -3.0e38f;
        }
        __syncthreads();
    }
    if (tid == 0) {
        float mx = wk[0];
        for (int i = 1; i < TOPK; i++) mx = fmaxf(mx, wk[i]);
        float e[TOPK], ssum = 0.f;
        for (int i = 0; i < TOPK; i++) { e[i] = expf(wk[i] - mx); ssum += e[i]; }
        for (int i = 0; i < TOPK; i++) g_nw[b * TOPK + i] = e[i] / ssum;
    }
}

// ---------------- K4: delayed-values aggregation ----------------
__global__ __launch_bounds__(128) void k4_out(const float* __restrict__ vals,
                                              float* __restrict__ out) {
    int bl = blockIdx.x;
    int b = bl / LL;
    int l = bl - b * LL;
    int tid = threadIdx.x;
    float nw[TOPK]; int dl[TOPK];
    #pragma unroll
    for (int k = 0; k < TOPK; k++) {
        nw[k] = g_nw[b * TOPK + k];
        dl[k] = g_delays[b * TOPK + k];
    }
    float4 acc = make_float4(0.f, 0.f, 0.f, 0.f);
    #pragma unroll
    for (int k = 0; k < TOPK; k++) {
        int ls = l + dl[k]; if (ls >= LL) ls -= LL;
        const float4* src = (const float4*)(vals + ((size_t)b * LL + ls) * HE);
        float4 v = src[tid];
        acc.x += nw[k] * v.x; acc.y += nw[k] * v.y;
        acc.z += nw[k] * v.z; acc.w += nw[k] * v.w;
    }
    ((float4*)(out + ((size_t)b * LL + l) * HE))[tid] = acc;
}

// ---------------- launch ----------------
extern "C" void kernel_launch(void* const* d_in, const int* in_sizes, int n_in,
                              void* d_out, int out_size) {
    const float* q  = (const float*)d_in[0];
    const float* kk = (const float*)d_in[1];
    const float* v  = (const float*)d_in[2];
    const float* sw = (const float*)d_in[3];
    const float* ff = (const float*)d_in[4];

    k0_init<<<48, 256>>>(sw, ff);
    dim3 g1(48, 64, 2);
    k1_ln<<<g1, 256>>>(q, kk);
    k2_corr<<<BHE, 256>>>();
    k3_topk<<<BB, 256>>>();
    k4_out<<<BB * LL, 128>>>(v, (float*)d_out);
}

// round 3
// speedup vs baseline: 1.6914x; 1.6914x over previous
#include <cuda_runtime.h>
#include <math.h>

#define BB 8
#define LL 1536
#define HH 8
#define EE 64
#define HE 512          // H*E
#define BHE 4096        // B*H*E
#define TOPK 7          // int(log(1536)) = 7

// ---------------- scratch (static __device__, no allocation) ----------------
__device__ float g_qr[(size_t)BHE * LL];   // layernormed q, (b,h,e,l)
__device__ float g_kr[(size_t)BHE * LL];   // layernormed k, (b,h,e,l)
__device__ float g_mean[BB * LL];          // sum over (h,e) of clipped corr
__device__ float g_scal[4];                // [0]=sigmoid(freq), [1..3]=softmax(scale_weights)
__device__ int   g_delays[BB * TOPK];
__device__ float g_nw[BB * TOPK];

// ---------------- K0: scalars + zero mean accumulator ----------------
__global__ void k0_init(const float* __restrict__ sw, const float* __restrict__ ff) {
    int idx = blockIdx.x * blockDim.x + threadIdx.x;
    for (int i = idx; i < BB * LL; i += gridDim.x * blockDim.x) g_mean[i] = 0.f;
    if (idx == 0) {
        g_scal[0] = 1.f / (1.f + expf(-ff[0]));
        float a = sw[0], b = sw[1], c = sw[2];
        float mx = fmaxf(a, fmaxf(b, c));
        float ea = expf(a - mx), eb = expf(b - mx), ec = expf(c - mx);
        float s = ea + eb + ec;
        g_scal[1] = ea / s; g_scal[2] = eb / s; g_scal[3] = ec / s;
    }
}

// ---------------- K1: LayerNorm over E + transpose to (b,h,e,l) ----------------
__global__ __launch_bounds__(256) void k1_ln(const float* __restrict__ q,
                                             const float* __restrict__ kk) {
    __shared__ float tile[32][EE + 1];
    __shared__ float mu[32], isd[32];
    int l0 = blockIdx.x * 32;
    int bh = blockIdx.y;                 // b*8 + h
    int b  = bh >> 3, h = bh & 7;
    const float* in = blockIdx.z ? kk : q;
    float* out      = blockIdx.z ? g_kr : g_qr;
    int tid = threadIdx.x;
    int e = tid & 63, r0 = tid >> 6;
    for (int r = r0; r < 32; r += 4)
        tile[r][e] = in[(((size_t)b * LL + l0 + r) * HH + h) * EE + e];
    __syncthreads();
    int lane = tid & 31, w = tid >> 5;
    for (int r = w; r < 32; r += 8) {
        float x0 = tile[r][lane], x1 = tile[r][lane + 32];
        float s = x0 + x1, s2 = x0 * x0 + x1 * x1;
        #pragma unroll
        for (int off = 16; off; off >>= 1) {
            s  += __shfl_down_sync(0xffffffffu, s,  off);
            s2 += __shfl_down_sync(0xffffffffu, s2, off);
        }
        if (lane == 0) {
            float m = s * (1.f / EE);
            float v = s2 * (1.f / EE) - m * m;
            mu[r] = m; isd[r] = rsqrtf(v + 1e-5f);
        }
    }
    __syncthreads();
    int li = tid & 31, e0 = tid >> 5;
    for (int ee = e0; ee < EE; ee += 8) {
        float val = (tile[li][ee] - mu[li]) * isd[li];
        out[(((size_t)bh) * EE + ee) * LL + l0 + li] = val;
    }
}

// ---------------- FFT: templated Stockham stages, SoA, twiddle LUT ----------------
// Twiddle table: tw[t] = exp(-2*pi*i*t/1536), t in [0,768).
// Stage twiddle w = exp(-2*pi*i*j/(R*L)) = tw[j * (1536/(R*L))].

template<int R, int M, int L>
__device__ __forceinline__ void fstage(const float* __restrict__ ar, const float* __restrict__ ai,
                                       float* __restrict__ br, float* __restrict__ bi,
                                       const float2* __restrict__ tw, int tid) {
    constexpr int NB   = L * M;            // butterflies; also the input stride
    constexpr int STEP = 1536 / (R * L);
    for (int t = tid; t < NB; t += 256) {
        int j = t / M;                     // compile-time M -> mul/shift
        int k = t - j * M;
        int wb = k + (M * R) * j;
        float2 w1 = tw[j * STEP];
        if (R == 4) {
            float c0r = ar[t],          c0i = ai[t];
            float c1r = ar[t + NB],     c1i = ai[t + NB];
            float c2r = ar[t + 2 * NB], c2i = ai[t + 2 * NB];
            float c3r = ar[t + 3 * NB], c3i = ai[t + 3 * NB];
            float t0r = c0r + c2r, t0i = c0i + c2i;
            float t1r = c0r - c2r, t1i = c0i - c2i;
            float t2r = c1r + c3r, t2i = c1i + c3i;
            float t3r = c1r - c3r, t3i = c1i - c3i;
            float d0r = t0r + t2r, d0i = t0i + t2i;
            float d2r = t0r - t2r, d2i = t0i - t2i;
            float d1r = t1r + t3i, d1i = t1i - t3r;   // t1 - i*t3
            float d3r = t1r - t3i, d3i = t1i + t3r;   // t1 + i*t3
            float w2r = w1.x * w1.x - w1.y * w1.y;
            float w2i = 2.f * w1.x * w1.y;
            float w3r = w2r * w1.x - w2i * w1.y;
            float w3i = w2r * w1.y + w2i * w1.x;
            br[wb]         = d0r;
            bi[wb]         = d0i;
            br[wb + M]     = d1r * w1.x - d1i * w1.y;
            bi[wb + M]     = d1r * w1.y + d1i * w1.x;
            br[wb + 2 * M] = d2r * w2r - d2i * w2i;
            bi[wb + 2 * M] = d2r * w2i + d2i * w2r;
            br[wb + 3 * M] = d3r * w3r - d3i * w3i;
            bi[wb + 3 * M] = d3r * w3i + d3i * w3r;
        } else if (R == 3) {
            float c0r = ar[t],          c0i = ai[t];
            float c1r = ar[t + NB],     c1i = ai[t + NB];
            float c2r = ar[t + 2 * NB], c2i = ai[t + 2 * NB];
            float t1r = c1r + c2r, t1i = c1i + c2i;
            float ur  = c0r - 0.5f * t1r, ui = c0i - 0.5f * t1i;
            const float s3 = 0.8660254037844386f;
            float vr = s3 * (c1r - c2r), vi = s3 * (c1i - c2i);
            float d0r = c0r + t1r, d0i = c0i + t1i;
            float d1r = ur + vi, d1i = ui - vr;        // u - i*v
            float d2r = ur - vi, d2i = ui + vr;        // u + i*v
            float w2r = w1.x * w1.x - w1.y * w1.y;
            float w2i = 2.f * w1.x * w1.y;
            br[wb]         = d0r;
            bi[wb]         = d0i;
            br[wb + M]     = d1r * w1.x - d1i * w1.y;
            bi[wb + M]     = d1r * w1.y + d1i * w1.x;
            br[wb + 2 * M] = d2r * w2r - d2i * w2i;
            bi[wb + 2 * M] = d2r * w2i + d2i * w2r;
        } else {  // R == 2
            float c0r = ar[t],      c0i = ai[t];
            float c1r = ar[t + NB], c1i = ai[t + NB];
            float d1r = c0r - c1r, d1i = c0i - c1i;
            br[wb]     = c0r + c1r;
            bi[wb]     = c0i + c1i;
            br[wb + M] = d1r * w1.x - d1i * w1.y;
            bi[wb + M] = d1r * w1.y + d1i * w1.x;
        }
    }
    __syncthreads();
}

// fft1536(x, y): 6 stages, result lands in x.
__device__ __forceinline__ void fft1536(float* xr, float* xi, float* yr, float* yi,
                                        const float2* tw, int tid) {
    fstage<3, 1,   512>(xr, xi, yr, yi, tw, tid);
    fstage<4, 3,   128>(yr, yi, xr, xi, tw, tid);
    fstage<4, 12,  32 >(xr, xi, yr, yi, tw, tid);
    fstage<4, 48,  8  >(yr, yi, xr, xi, tw, tid);
    fstage<4, 192, 2  >(xr, xi, yr, yi, tw, tid);
    fstage<2, 768, 1  >(yr, yi, xr, xi, tw, tid);
}

// fft768(x, y): 5 stages, result lands in y.
__device__ __forceinline__ void fft768(float* xr, float* xi, float* yr, float* yi,
                                       const float2* tw, int tid) {
    fstage<3, 1,   256>(xr, xi, yr, yi, tw, tid);
    fstage<4, 3,   64 >(yr, yi, xr, xi, tw, tid);
    fstage<4, 12,  16 >(xr, xi, yr, yi, tw, tid);
    fstage<4, 48,  4  >(yr, yi, xr, xi, tw, tid);
    fstage<4, 192, 1  >(xr, xi, yr, yi, tw, tid);
}

// fft384(x, y): 5 stages, result lands in y.
__device__ __forceinline__ void fft384(float* xr, float* xi, float* yr, float* yi,
                                       const float2* tw, int tid) {
    fstage<3, 1,   128>(xr, xi, yr, yi, tw, tid);
    fstage<4, 3,   32 >(yr, yi, xr, xi, tw, tid);
    fstage<4, 12,  8  >(xr, xi, yr, yi, tw, tid);
    fstage<4, 48,  2  >(yr, yi, xr, xi, tw, tid);
    fstage<2, 192, 1  >(xr, xi, yr, yi, tw, tid);
}

// Hermitian split of packed FFT Z = Q + iK, whitened cross-spectrum into (br,bi)
__device__ __forceinline__ void herm_split(const float* __restrict__ ar, const float* __restrict__ ai,
                                           float* __restrict__ br, float* __restrict__ bi,
                                           int N, float f, int tid) {
    int half = N >> 1;
    for (int w = tid; w <= half; w += 256) {
        int iw = (w == 0) ? 0 : N - w;
        float Zwr = ar[w],  Zwi = ai[w];
        float Zmr = ar[iw], Zmi = ai[iw];
        float Qx = 0.5f * (Zwr + Zmr), Qy = 0.5f * (Zwi - Zmi);
        float Kx = 0.5f * (Zwi + Zmi), Ky = -0.5f * (Zwr - Zmr);
        float kmag = sqrtf(Kx * Kx + Ky * Ky);
        float sc   = f * f / (f * kmag + 1e-8f);
        float Rx = (Qx * Kx + Qy * Ky) * sc;
        float Ry = (Qy * Kx - Qx * Ky) * sc;
        br[w] = Rx; bi[w] = Ry;
        if (w > 0 && w < half) { br[N - w] = Rx; bi[N - w] = -Ry; }
    }
    __syncthreads();
}

// ---------------- K2: per-(b,h,e) 3-scale whitened autocorrelation ----------------
__global__ __launch_bounds__(256) void k2_corr() {
    extern __shared__ float sm[];
    float* sq   = sm;             // 1536
    float* sk   = sm + 1536;      // 1536
    float* sacc = sm + 3072;      // 1536
    float* Ar   = sm + 4608;      // 1536
    float* Ai   = sm + 6144;      // 1536
    float* Br   = sm + 7680;      // 1536
    float* Bi   = sm + 9216;      // 1536
    float2* tw  = (float2*)(sm + 10752);  // 768 float2 (byte offset 43008, 8B-aligned)

    int tid = threadIdx.x;
    int bhe = blockIdx.x;
    int b = bhe >> 9;   // / (H*E)
    const float* qrow = g_qr + (size_t)bhe * LL;
    const float* krow = g_kr + (size_t)bhe * LL;

    // twiddle LUT (once per CTA)
    const float TWO_PI_OVER = -6.283185307179586f / 1536.f;
    for (int t = tid; t < 768; t += 256) {
        float s, c; __sincosf(TWO_PI_OVER * (float)t, &s, &c);
        tw[t] = make_float2(c, s);
    }
    for (int i = tid; i < LL; i += 256) {
        sq[i] = qrow[i]; sk[i] = krow[i]; sacc[i] = 0.f;
    }
    float f = g_scal[0];
    __syncthreads();

    // ======== scale 1 (N=1536) ========
    for (int n = tid; n < 1536; n += 256) { Ar[n] = sq[n]; Ai[n] = sk[n]; }
    __syncthreads();
    fft1536(Ar, Ai, Br, Bi, tw, tid);            // Z in A
    herm_split(Ar, Ai, Br, Bi, 1536, f, tid);    // R in B
    fft1536(Br, Bi, Ar, Ai, tw, tid);            // result in B
    {
        float wgt = g_scal[1] * (1.f / 1536.f);
        for (int l = tid; l < LL; l += 256) {
            int idx = (l == 0) ? 0 : 1536 - l;
            sacc[l] += wgt * Br[idx];
        }
    }
    __syncthreads();

    // ======== scale 2 (N=768) ========
    for (int n = tid; n < 768; n += 256) {
        Ar[n] = 0.5f * (sq[2 * n] + sq[2 * n + 1]);
        Ai[n] = 0.5f * (sk[2 * n] + sk[2 * n + 1]);
    }
    __syncthreads();
    fft768(Ar, Ai, Br, Bi, tw, tid);             // Z in B
    herm_split(Br, Bi, Ar, Ai, 768, f, tid);     // R in A
    fft768(Ar, Ai, Br, Bi, tw, tid);             // result in B
    {
        float wgt = g_scal[2] * (1.f / 768.f);
        const int N = 768;
        for (int l = tid; l < LL; l += 256) {
            float coords = ((float)l + 0.5f) * 0.5f - 0.5f;
            coords = fminf(fmaxf(coords, 0.f), (float)(N - 1));
            int lo = (int)floorf(coords);
            int hi = min(lo + 1, N - 1);
            float fr = coords - (float)lo;
            float clo = Br[(lo == 0) ? 0 : N - lo];
            float chi = Br[(hi == 0) ? 0 : N - hi];
            sacc[l] += wgt * (clo * (1.f - fr) + chi * fr);
        }
    }
    __syncthreads();

    // ======== scale 4 (N=384) ========
    for (int n = tid; n < 384; n += 256) {
        Ar[n] = 0.25f * (sq[4 * n] + sq[4 * n + 1] + sq[4 * n + 2] + sq[4 * n + 3]);
        Ai[n] = 0.25f * (sk[4 * n] + sk[4 * n + 1] + sk[4 * n + 2] + sk[4 * n + 3]);
    }
    __syncthreads();
    fft384(Ar, Ai, Br, Bi, tw, tid);             // Z in B
    herm_split(Br, Bi, Ar, Ai, 384, f, tid);     // R in A
    fft384(Ar, Ai, Br, Bi, tw, tid);             // result in B
    {
        float wgt = g_scal[3] * (1.f / 384.f);
        const int N = 384;
        for (int l = tid; l < LL; l += 256) {
            float coords = ((float)l + 0.5f) * 0.25f - 0.5f;
            coords = fminf(fmaxf(coords, 0.f), (float)(N - 1));
            int lo = (int)floorf(coords);
            int hi = min(lo + 1, N - 1);
            float fr = coords - (float)lo;
            float clo = Br[(lo == 0) ? 0 : N - lo];
            float chi = Br[(hi == 0) ? 0 : N - hi];
            sacc[l] += wgt * (clo * (1.f - fr) + chi * fr);
        }
    }
    __syncthreads();

    for (int l = tid; l < LL; l += 256) {
        float v = fminf(fmaxf(sacc[l], -10.f), 10.f);
        atomicAdd(&g_mean[b * LL + l], v);
    }
}

// ---------------- K3: per-batch top-7 + softmax (register-cached) ----------------
__global__ __launch_bounds__(256) void k3_topk() {
    __shared__ float swv[8];
    __shared__ int   swi[8];
    __shared__ float s_wk[TOPK];
    __shared__ int   s_bi[TOPK];
    __shared__ int   s_sel;
    int b = blockIdx.x;
    int tid = threadIdx.x;
    int lane = tid & 31, w = tid >> 5;
    float v[6];
    #pragma unroll
    for (int i = 0; i < 6; i++)
        v[i] = g_mean[b * LL + tid + 256 * i] * (1.f / HE);

    for (int it = 0; it < TOPK; it++) {
        float best = -3.0e38f; int bi = 0;
        #pragma unroll
        for (int i = 0; i < 6; i++) {
            if (v[i] > best) { best = v[i]; bi = tid + 256 * i; }
        }
        #pragma unroll
        for (int off = 16; off; off >>= 1) {
            float ov = __shfl_down_sync(0xffffffffu, best, off);
            int   oi = __shfl_down_sync(0xffffffffu, bi,   off);
            if (ov > best || (ov == best && oi < bi)) { best = ov; bi = oi; }
        }
        if (lane == 0) { swv[w] = best; swi[w] = bi; }
        __syncthreads();
        if (tid == 0) {
            float bb = swv[0]; int bj = swi[0];
            #pragma unroll
            for (int q = 1; q < 8; q++)
                if (swv[q] > bb || (swv[q] == bb && swi[q] < bj)) { bb = swv[q]; bj = swi[q]; }
            s_wk[it] = bb; s_bi[it] = bj; s_sel = bj;
        }
        __syncthreads();
        int sel = s_sel;
        if ((sel & 255) == tid) v[sel >> 8] = -3.0e38f;
        // no extra sync needed: next swv write is after an argmax preceded by a sync
    }
    if (tid == 0) {
        float mx = s_wk[0];
        #pragma unroll
        for (int i = 1; i < TOPK; i++) mx = fmaxf(mx, s_wk[i]);
        float e[TOPK], ssum = 0.f;
        #pragma unroll
        for (int i = 0; i < TOPK; i++) { e[i] = expf(s_wk[i] - mx); ssum += e[i]; }
        #pragma unroll
        for (int i = 0; i < TOPK; i++) {
            g_nw[b * TOPK + i] = e[i] / ssum;
            g_delays[b * TOPK + i] = s_bi[i];
        }
    }
}

// ---------------- K4: delayed-values aggregation ----------------
__global__ __launch_bounds__(128) void k4_out(const float* __restrict__ vals,
                                              float* __restrict__ out) {
    int bl = blockIdx.x;
    int b = bl / LL;
    int l = bl - b * LL;
    int tid = threadIdx.x;
    float nw[TOPK]; int dl[TOPK];
    #pragma unroll
    for (int k = 0; k < TOPK; k++) {
        nw[k] = g_nw[b * TOPK + k];
        dl[k] = g_delays[b * TOPK + k];
    }
    float4 acc = make_float4(0.f, 0.f, 0.f, 0.f);
    #pragma unroll
    for (int k = 0; k < TOPK; k++) {
        int ls = l + dl[k]; if (ls >= LL) ls -= LL;
        const float4* src = (const float4*)(vals + ((size_t)b * LL + ls) * HE);
        float4 v = src[tid];
        acc.x += nw[k] * v.x; acc.y += nw[k] * v.y;
        acc.z += nw[k] * v.z; acc.w += nw[k] * v.w;
    }
    ((float4*)(out + ((size_t)b * LL + l) * HE))[tid] = acc;
}

// ---------------- launch ----------------
extern "C" void kernel_launch(void* const* d_in, const int* in_sizes, int n_in,
                              void* d_out, int out_size) {
    const float* q  = (const float*)d_in[0];
    const float* kk = (const float*)d_in[1];
    const float* v  = (const float*)d_in[2];
    const float* sw = (const float*)d_in[3];
    const float* ff = (const float*)d_in[4];

    const int K2_SMEM = 49152;  // 7*1536*4 + 768*8 = 43008+6144 = 49152 (== default 48KB cap)

    k0_init<<<48, 256>>>(sw, ff);
    dim3 g1(48, 64, 2);
    k1_ln<<<g1, 256>>>(q, kk);
    k2_corr<<<BHE, 256, K2_SMEM>>>();
    k3_topk<<<BB, 256>>>();
    k4_out<<<BB * LL, 128>>>(v, (float*)d_out);
}

// round 4
// speedup vs baseline: 1.7642x; 1.0430x over previous
#include <cuda_runtime.h>
#include <math.h>

#define BB 8
#define LL 1536
#define HH 8
#define EE 64
#define HE 512          // H*E
#define BHE 4096        // B*H*E
#define TOPK 7          // int(log(1536)) = 7

// ---------------- scratch (static __device__, no allocation) ----------------
__device__ float g_qr[(size_t)BHE * LL];   // layernormed q, (b,h,e,l)
__device__ float g_kr[(size_t)BHE * LL];   // layernormed k, (b,h,e,l)
__device__ float g_mean[BB * LL];          // sum over (h,e) of clipped corr
__device__ float g_scal[4];                // [0]=sigmoid(freq), [1..3]=softmax(scale_weights)
__device__ int   g_delays[BB * TOPK];
__device__ float g_nw[BB * TOPK];

// ---------------- K0: scalars + zero mean accumulator ----------------
__global__ void k0_init(const float* __restrict__ sw, const float* __restrict__ ff) {
    int idx = blockIdx.x * blockDim.x + threadIdx.x;
    for (int i = idx; i < BB * LL; i += gridDim.x * blockDim.x) g_mean[i] = 0.f;
    if (idx == 0) {
        g_scal[0] = 1.f / (1.f + expf(-ff[0]));
        float a = sw[0], b = sw[1], c = sw[2];
        float mx = fmaxf(a, fmaxf(b, c));
        float ea = expf(a - mx), eb = expf(b - mx), ec = expf(c - mx);
        float s = ea + eb + ec;
        g_scal[1] = ea / s; g_scal[2] = eb / s; g_scal[3] = ec / s;
    }
}

// ---------------- K1: LayerNorm over E + transpose to (b,h,e,l) ----------------
__global__ __launch_bounds__(256) void k1_ln(const float* __restrict__ q,
                                             const float* __restrict__ kk) {
    __shared__ float tile[32][EE + 1];
    __shared__ float mu[32], isd[32];
    int l0 = blockIdx.x * 32;
    int bh = blockIdx.y;                 // b*8 + h
    int b  = bh >> 3, h = bh & 7;
    const float* in = blockIdx.z ? kk : q;
    float* out      = blockIdx.z ? g_kr : g_qr;
    int tid = threadIdx.x;
    int e = tid & 63, r0 = tid >> 6;
    for (int r = r0; r < 32; r += 4)
        tile[r][e] = in[(((size_t)b * LL + l0 + r) * HH + h) * EE + e];
    __syncthreads();
    int lane = tid & 31, w = tid >> 5;
    for (int r = w; r < 32; r += 8) {
        float x0 = tile[r][lane], x1 = tile[r][lane + 32];
        float s = x0 + x1, s2 = x0 * x0 + x1 * x1;
        #pragma unroll
        for (int off = 16; off; off >>= 1) {
            s  += __shfl_down_sync(0xffffffffu, s,  off);
            s2 += __shfl_down_sync(0xffffffffu, s2, off);
        }
        if (lane == 0) {
            float m = s * (1.f / EE);
            float v = s2 * (1.f / EE) - m * m;
            mu[r] = m; isd[r] = rsqrtf(v + 1e-5f);
        }
    }
    __syncthreads();
    int li = tid & 31, e0 = tid >> 5;
    for (int ee = e0; ee < EE; ee += 8) {
        float val = (tile[li][ee] - mu[li]) * isd[li];
        out[(((size_t)bh) * EE + ee) * LL + l0 + li] = val;
    }
}

// ---------------- FFT: templated Stockham stages, SoA, twiddle LUT ----------------
// tw[t] = exp(-2*pi*i*t/1536), t in [0,768). Stage twiddle = tw[j * (1536/(R*L))].

template<int R, int M, int L>
__device__ __forceinline__ void fstage(const float* __restrict__ ar, const float* __restrict__ ai,
                                       float* __restrict__ br, float* __restrict__ bi,
                                       const float2* __restrict__ tw, int tid) {
    constexpr int NB   = L * M;            // butterflies; also the input stride
    constexpr int STEP = 1536 / (R * L);
    for (int t = tid; t < NB; t += 256) {
        int j = t / M;                     // compile-time M -> mul/shift
        int k = t - j * M;
        int wb = k + (M * R) * j;
        float2 w1 = tw[j * STEP];
        if (R == 4) {
            float c0r = ar[t],          c0i = ai[t];
            float c1r = ar[t + NB],     c1i = ai[t + NB];
            float c2r = ar[t + 2 * NB], c2i = ai[t + 2 * NB];
            float c3r = ar[t + 3 * NB], c3i = ai[t + 3 * NB];
            float t0r = c0r + c2r, t0i = c0i + c2i;
            float t1r = c0r - c2r, t1i = c0i - c2i;
            float t2r = c1r + c3r, t2i = c1i + c3i;
            float t3r = c1r - c3r, t3i = c1i - c3i;
            float d0r = t0r + t2r, d0i = t0i + t2i;
            float d2r = t0r - t2r, d2i = t0i - t2i;
            float d1r = t1r + t3i, d1i = t1i - t3r;   // t1 - i*t3
            float d3r = t1r - t3i, d3i = t1i + t3r;   // t1 + i*t3
            float w2r = w1.x * w1.x - w1.y * w1.y;
            float w2i = 2.f * w1.x * w1.y;
            float w3r = w2r * w1.x - w2i * w1.y;
            float w3i = w2r * w1.y + w2i * w1.x;
            br[wb]         = d0r;
            bi[wb]         = d0i;
            br[wb + M]     = d1r * w1.x - d1i * w1.y;
            bi[wb + M]     = d1r * w1.y + d1i * w1.x;
            br[wb + 2 * M] = d2r * w2r - d2i * w2i;
            bi[wb + 2 * M] = d2r * w2i + d2i * w2r;
            br[wb + 3 * M] = d3r * w3r - d3i * w3i;
            bi[wb + 3 * M] = d3r * w3i + d3i * w3r;
        } else if (R == 3) {
            float c0r = ar[t],          c0i = ai[t];
            float c1r = ar[t + NB],     c1i = ai[t + NB];
            float c2r = ar[t + 2 * NB], c2i = ai[t + 2 * NB];
            float t1r = c1r + c2r, t1i = c1i + c2i;
            float ur  = c0r - 0.5f * t1r, ui = c0i - 0.5f * t1i;
            const float s3 = 0.8660254037844386f;
            float vr = s3 * (c1r - c2r), vi = s3 * (c1i - c2i);
            float d0r = c0r + t1r, d0i = c0i + t1i;
            float d1r = ur + vi, d1i = ui - vr;        // u - i*v
            float d2r = ur - vi, d2i = ui + vr;        // u + i*v
            float w2r = w1.x * w1.x - w1.y * w1.y;
            float w2i = 2.f * w1.x * w1.y;
            br[wb]         = d0r;
            bi[wb]         = d0i;
            br[wb + M]     = d1r * w1.x - d1i * w1.y;
            bi[wb + M]     = d1r * w1.y + d1i * w1.x;
            br[wb + 2 * M] = d2r * w2r - d2i * w2i;
            bi[wb + 2 * M] = d2r * w2i + d2i * w2r;
        } else {  // R == 2
            float c0r = ar[t],      c0i = ai[t];
            float c1r = ar[t + NB], c1i = ai[t + NB];
            float d1r = c0r - c1r, d1i = c0i - c1i;
            br[wb]     = c0r + c1r;
            bi[wb]     = c0i + c1i;
            br[wb + M] = d1r * w1.x - d1i * w1.y;
            bi[wb + M] = d1r * w1.y + d1i * w1.x;
        }
    }
    __syncthreads();
}

// fft1536: 6 stages, result lands in x.
__device__ __forceinline__ void fft1536(float* xr, float* xi, float* yr, float* yi,
                                        const float2* tw, int tid) {
    fstage<3, 1,   512>(xr, xi, yr, yi, tw, tid);
    fstage<4, 3,   128>(yr, yi, xr, xi, tw, tid);
    fstage<4, 12,  32 >(xr, xi, yr, yi, tw, tid);
    fstage<4, 48,  8  >(yr, yi, xr, xi, tw, tid);
    fstage<4, 192, 2  >(xr, xi, yr, yi, tw, tid);
    fstage<2, 768, 1  >(yr, yi, xr, xi, tw, tid);
}

// fft768: 5 stages, result lands in y.
__device__ __forceinline__ void fft768(float* xr, float* xi, float* yr, float* yi,
                                       const float2* tw, int tid) {
    fstage<3, 1,   256>(xr, xi, yr, yi, tw, tid);
    fstage<4, 3,   64 >(yr, yi, xr, xi, tw, tid);
    fstage<4, 12,  16 >(xr, xi, yr, yi, tw, tid);
    fstage<4, 48,  4  >(yr, yi, xr, xi, tw, tid);
    fstage<4, 192, 1  >(xr, xi, yr, yi, tw, tid);
}

// fft384: 5 stages, result lands in y.
__device__ __forceinline__ void fft384(float* xr, float* xi, float* yr, float* yi,
                                       const float2* tw, int tid) {
    fstage<3, 1,   128>(xr, xi, yr, yi, tw, tid);
    fstage<4, 3,   32 >(yr, yi, xr, xi, tw, tid);
    fstage<4, 12,  8  >(xr, xi, yr, yi, tw, tid);
    fstage<4, 48,  2  >(yr, yi, xr, xi, tw, tid);
    fstage<2, 192, 1  >(xr, xi, yr, yi, tw, tid);
}

// fft192: 4 stages, result lands in x.
__device__ __forceinline__ void fft192(float* xr, float* xi, float* yr, float* yi,
                                       const float2* tw, int tid) {
    fstage<3, 1,   64 >(xr, xi, yr, yi, tw, tid);
    fstage<4, 3,   16 >(yr, yi, xr, xi, tw, tid);
    fstage<4, 12,  4  >(xr, xi, yr, yi, tw, tid);
    fstage<4, 48,  1  >(yr, yi, xr, xi, tw, tid);
}

// Hermitian split of packed FFT Z = Q + iK; whitened cross-spectrum R into
// (br,bi) for w = 0..N/2 ONLY (no mirror — inverse uses the half-spectrum form).
__device__ __forceinline__ void herm_split(const float* __restrict__ ar, const float* __restrict__ ai,
                                           float* __restrict__ br, float* __restrict__ bi,
                                           int N, float f, int tid) {
    int half = N >> 1;
    for (int w = tid; w <= half; w += 256) {
        int iw = (w == 0) ? 0 : N - w;
        float Zwr = ar[w],  Zwi = ai[w];
        float Zmr = ar[iw], Zmi = ai[iw];
        float Qx = 0.5f * (Zwr + Zmr), Qy = 0.5f * (Zwi - Zmi);
        float Kx = 0.5f * (Zwi + Zmi), Ky = -0.5f * (Zwr - Zmr);
        float kmag = sqrtf(Kx * Kx + Ky * Ky);
        float sc   = f * f / (f * kmag + 1e-8f);
        br[w] = (Qx * Kx + Qy * Ky) * sc;
        bi[w] = (Qy * Kx - Qx * Ky) * sc;
    }
    __syncthreads();
}

// Build packed half-length inverse input z = E + i*O from half-spectrum R[0..M]
//   E[m] = (R[m] + conj(R[M-m]))/2            (m=0: R[M] unconjugated)
//   O[m] = (R[m] - conj(R[M-m]))/2 * e^{+2*pi*i*m/N},  N = 2M
// e^{+2*pi*i*m/N} = conj(tw[m * (1536/N)]).
__device__ __forceinline__ void zbuild(const float* __restrict__ br, const float* __restrict__ bi,
                                       float* __restrict__ zr, float* __restrict__ zi,
                                       int M, int stepN, const float2* __restrict__ tw, int tid) {
    for (int m = tid; m < M; m += 256) {
        int im = M - m;                      // m=0 -> M
        float Rr = br[m],  Ri = bi[m];
        float Cr = br[im], Ci = bi[im];
        if (m) Ci = -Ci;                     // conj for m >= 1
        float Er = 0.5f * (Rr + Cr), Ei = 0.5f * (Ri + Ci);
        float Dr = 0.5f * (Rr - Cr), Di = 0.5f * (Ri - Ci);
        float2 t = tw[m * stepN];
        float wr = t.x, wi = -t.y;           // e^{+2*pi*i*m/N}
        float Or = Dr * wr - Di * wi;
        float Oi = Dr * wi + Di * wr;
        zr[m] = Er - Oi;
        zi[m] = Ei + Or;
    }
    __syncthreads();
}

// c[idx] from forward-FFT'd z (length M): p=idx/2, q=(M-p)%M;
// even idx -> Re zf[q]/M, odd -> Im zf[q]/M (1/M folded into caller's weight).
__device__ __forceinline__ float cval(const float* zr, const float* zi, int M, int idx) {
    int p = idx >> 1;
    int q = p ? (M - p) : 0;
    return (idx & 1) ? zi[q] : zr[q];
}

// ---------------- K2: per-(b,h,e) 3-scale whitened autocorrelation ----------------
__global__ __launch_bounds__(256) void k2_corr() {
    extern __shared__ float sm[];
    float* sq   = sm;             // 1536
    float* sk   = sm + 1536;      // 1536
    float* sacc = sm + 3072;      // 1536
    float* Ar   = sm + 4608;      // 1536
    float* Ai   = sm + 6144;      // 1536
    float* Br   = sm + 7680;      // 1536
    float* Bi   = sm + 9216;      // 1536
    float2* tw  = (float2*)(sm + 10752);  // 768 float2

    int tid = threadIdx.x;
    int bhe = blockIdx.x;
    int b = bhe >> 9;
    const float* qrow = g_qr + (size_t)bhe * LL;
    const float* krow = g_kr + (size_t)bhe * LL;

    const float TWO_PI_OVER = -6.283185307179586f / 1536.f;
    for (int t = tid; t < 768; t += 256) {
        float s, c; __sincosf(TWO_PI_OVER * (float)t, &s, &c);
        tw[t] = make_float2(c, s);
    }
    for (int i = tid; i < LL; i += 256) {
        sq[i] = qrow[i]; sk[i] = krow[i]; sacc[i] = 0.f;
    }
    float f = g_scal[0];
    __syncthreads();

    // ======== scale 1 (N=1536, M=768) ========
    for (int n = tid; n < 1536; n += 256) { Ar[n] = sq[n]; Ai[n] = sk[n]; }
    __syncthreads();
    fft1536(Ar, Ai, Br, Bi, tw, tid);            // Z in A
    herm_split(Ar, Ai, Br, Bi, 1536, f, tid);    // R[0..768] in B
    zbuild(Br, Bi, Ar, Ai, 768, 1, tw, tid);     // z in A
    fft768(Ar, Ai, Br, Bi, tw, tid);             // zf in B
    {
        float wgt = g_scal[1] * (1.f / 768.f);
        for (int l = tid; l < LL; l += 256)
            sacc[l] += wgt * cval(Br, Bi, 768, l);
    }
    __syncthreads();

    // ======== scale 2 (N=768, M=384) ========
    for (int n = tid; n < 768; n += 256) {
        Ar[n] = 0.5f * (sq[2 * n] + sq[2 * n + 1]);
        Ai[n] = 0.5f * (sk[2 * n] + sk[2 * n + 1]);
    }
    __syncthreads();
    fft768(Ar, Ai, Br, Bi, tw, tid);             // Z in B
    herm_split(Br, Bi, Ar, Ai, 768, f, tid);     // R[0..384] in A
    zbuild(Ar, Ai, Br, Bi, 384, 2, tw, tid);     // z in B
    fft384(Br, Bi, Ar, Ai, tw, tid);             // zf in A
    {
        float wgt = g_scal[2] * (1.f / 384.f);
        const int N = 768;
        for (int l = tid; l < LL; l += 256) {
            float coords = ((float)l + 0.5f) * 0.5f - 0.5f;
            coords = fminf(fmaxf(coords, 0.f), (float)(N - 1));
            int lo = (int)floorf(coords);
            int hi = min(lo + 1, N - 1);
            float fr = coords - (float)lo;
            float clo = cval(Ar, Ai, 384, lo);
            float chi = cval(Ar, Ai, 384, hi);
            sacc[l] += wgt * (clo * (1.f - fr) + chi * fr);
        }
    }
    __syncthreads();

    // ======== scale 4 (N=384, M=192) ========
    for (int n = tid; n < 384; n += 256) {
        Ar[n] = 0.25f * (sq[4 * n] + sq[4 * n + 1] + sq[4 * n + 2] + sq[4 * n + 3]);
        Ai[n] = 0.25f * (sk[4 * n] + sk[4 * n + 1] + sk[4 * n + 2] + sk[4 * n + 3]);
    }
    __syncthreads();
    fft384(Ar, Ai, Br, Bi, tw, tid);             // Z in B
    herm_split(Br, Bi, Ar, Ai, 384, f, tid);     // R[0..192] in A
    zbuild(Ar, Ai, Br, Bi, 192, 4, tw, tid);     // z in B
    fft192(Br, Bi, Ar, Ai, tw, tid);             // zf in B
    {
        float wgt = g_scal[3] * (1.f / 192.f);
        const int N = 384;
        for (int l = tid; l < LL; l += 256) {
            float coords = ((float)l + 0.5f) * 0.25f - 0.5f;
            coords = fminf(fmaxf(coords, 0.f), (float)(N - 1));
            int lo = (int)floorf(coords);
            int hi = min(lo + 1, N - 1);
            float fr = coords - (float)lo;
            float clo = cval(Br, Bi, 192, lo);
            float chi = cval(Br, Bi, 192, hi);
            sacc[l] += wgt * (clo * (1.f - fr) + chi * fr);
        }
    }
    __syncthreads();

    for (int l = tid; l < LL; l += 256) {
        float v = fminf(fmaxf(sacc[l], -10.f), 10.f);
        atomicAdd(&g_mean[b * LL + l], v);
    }
}

// ---------------- K3: per-batch top-7 + softmax (single warp, shuffle-only) ----------------
__global__ __launch_bounds__(32) void k3_topk() {
    int b = blockIdx.x;
    int lane = threadIdx.x;
    float v[48];
    #pragma unroll
    for (int i = 0; i < 48; i++)
        v[i] = g_mean[b * LL + lane + 32 * i] * (1.f / HE);

    float wk[TOPK]; int dk[TOPK];
    for (int it = 0; it < TOPK; it++) {
        float best = -3.0e38f; int bi = 0;
        #pragma unroll
        for (int i = 0; i < 48; i++)
            if (v[i] > best) { best = v[i]; bi = lane + 32 * i; }
        #pragma unroll
        for (int off = 16; off; off >>= 1) {
            float ov = __shfl_down_sync(0xffffffffu, best, off);
            int   oi = __shfl_down_sync(0xffffffffu, bi,   off);
            if (ov > best || (ov == best && oi < bi)) { best = ov; bi = oi; }
        }
        best = __shfl_sync(0xffffffffu, best, 0);
        bi   = __shfl_sync(0xffffffffu, bi,   0);
        wk[it] = best; dk[it] = bi;
        if ((bi & 31) == lane) v[bi >> 5] = -3.0e38f;
    }
    if (lane == 0) {
        float mx = wk[0];
        #pragma unroll
        for (int i = 1; i < TOPK; i++) mx = fmaxf(mx, wk[i]);
        float e[TOPK], ssum = 0.f;
        #pragma unroll
        for (int i = 0; i < TOPK; i++) { e[i] = expf(wk[i] - mx); ssum += e[i]; }
        #pragma unroll
        for (int i = 0; i < TOPK; i++) {
            g_nw[b * TOPK + i] = e[i] / ssum;
            g_delays[b * TOPK + i] = dk[i];
        }
    }
}

// ---------------- K4: delayed-values aggregation ----------------
__global__ __launch_bounds__(128) void k4_out(const float* __restrict__ vals,
                                              float* __restrict__ out) {
    int bl = blockIdx.x;
    int b = bl / LL;
    int l = bl - b * LL;
    int tid = threadIdx.x;
    float nw[TOPK]; int dl[TOPK];
    #pragma unroll
    for (int k = 0; k < TOPK; k++) {
        nw[k] = g_nw[b * TOPK + k];
        dl[k] = g_delays[b * TOPK + k];
    }
    float4 acc = make_float4(0.f, 0.f, 0.f, 0.f);
    #pragma unroll
    for (int k = 0; k < TOPK; k++) {
        int ls = l + dl[k]; if (ls >= LL) ls -= LL;
        const float4* src = (const float4*)(vals + ((size_t)b * LL + ls) * HE);
        float4 v = src[tid];
        acc.x += nw[k] * v.x; acc.y += nw[k] * v.y;
        acc.z += nw[k] * v.z; acc.w += nw[k] * v.w;
    }
    ((float4*)(out + ((size_t)b * LL + l) * HE))[tid] = acc;
}

// ---------------- launch ----------------
extern "C" void kernel_launch(void* const* d_in, const int* in_sizes, int n_in,
                              void* d_out, int out_size) {
    const float* q  = (const float*)d_in[0];
    const float* kk = (const float*)d_in[1];
    const float* v  = (const float*)d_in[2];
    const float* sw = (const float*)d_in[3];
    const float* ff = (const float*)d_in[4];

    const int K2_SMEM = 49152;  // 7*1536*4 + 768*8 = 49152 (== default 48KB cap)

    k0_init<<<48, 256>>>(sw, ff);
    dim3 g1(48, 64, 2);
    k1_ln<<<g1, 256>>>(q, kk);
    k2_corr<<<BHE, 256, K2_SMEM>>>();
    k3_topk<<<BB, 32>>>();
    k4_out<<<BB * LL, 128>>>(v, (float*)d_out);
}